// round 13
// baseline (speedup 1.0000x reference)
#include <cuda_runtime.h>
#include <cuda_fp16.h>
#include <cuda_bf16.h>
#include <mma.h>
#include <math.h>

using namespace nvcuda;

#define N_NODES 50000
#define N_EDGES 1600000
#define IN_F    256
#define OUT_F   128
#define ALPHA   0.2f
#define EPSV    1e-9f

// GEMM tiling: 128x128 block tile, BK=16, double-buffered smem
#define GBM 128
#define GBN 128
#define GBK 16
#define N_PAD 50048   // 391 blocks * 128 rows

// scan config
#define SCAN_BS 256
#define SCAN_NB ((N_NODES + SCAN_BS - 1) / SCAN_BS)   // 196

// ---------------- scratch (device globals; no allocations allowed) ----------
__device__ float  g_h[(size_t)N_PAD * OUT_F];
__device__ __half g_hh[(size_t)N_NODES * OUT_F];
__device__ float  g_ssrc[N_NODES];
__device__ float  g_sdst[N_NODES];
__device__ int    g_deg[N_NODES];
__device__ int    g_off[N_NODES + 1];
__device__ int    g_cursor[N_NODES];
__device__ int    g_part[SCAN_NB];
__device__ int2   g_edge[N_EDGES];    // packed (dst, w bits)

// ---------------- GEMM: h = x @ W  (tf32, double-buffered) ------------------
__global__ __launch_bounds__(256) void gemm_tf32_kernel(
    const float* __restrict__ x, const float* __restrict__ W,
    float* __restrict__ h, int N)
{
    __shared__ float As[2][GBM][GBK + 4];   // 2*128*20*4 = 20.5 KB
    __shared__ float Bs[2][GBK][GBN];       // 2*16*128*4 = 16 KB

    const int tid = threadIdx.x;
    const int wid = tid >> 5;
    const int wm = wid >> 2;       // 0..1 -> 64 rows each
    const int wn = wid & 3;        // 0..3 -> 32 cols each
    const int row0 = blockIdx.x * GBM;

    const int ar0 = tid >> 2;
    const int ac  = (tid & 3) * 4;
    const int br0 = tid >> 5;
    const int bc  = (tid & 31) * 4;

    wmma::fragment<wmma::accumulator, 16, 16, 8, float> acc[4][2];
#pragma unroll
    for (int i = 0; i < 4; i++)
#pragma unroll
        for (int j = 0; j < 2; j++) wmma::fill_fragment(acc[i][j], 0.f);

    // preload chunk 0 into buffer 0
#pragma unroll
    for (int i = 0; i < 2; i++) {
        int grow = row0 + ar0 + i * 64; if (grow >= N) grow = N - 1;
        *reinterpret_cast<float4*>(&As[0][ar0 + i * 64][ac]) =
            *reinterpret_cast<const float4*>(x + (size_t)grow * IN_F + ac);
        *reinterpret_cast<float4*>(&Bs[0][br0 + i * 8][bc]) =
            *reinterpret_cast<const float4*>(W + (size_t)(br0 + i * 8) * GBN + bc);
    }
    __syncthreads();

    const int NIT = IN_F / GBK;   // 16
    for (int it = 0; it < NIT; it++) {
        const int cur = it & 1;
        float4 a_reg[2], b_reg[2];
        if (it + 1 < NIT) {
            const int k0 = (it + 1) * GBK;
#pragma unroll
            for (int i = 0; i < 2; i++) {
                int grow = row0 + ar0 + i * 64; if (grow >= N) grow = N - 1;
                a_reg[i] = *reinterpret_cast<const float4*>(x + (size_t)grow * IN_F + k0 + ac);
                b_reg[i] = *reinterpret_cast<const float4*>(W + (size_t)(k0 + br0 + i * 8) * GBN + bc);
            }
        }

#pragma unroll
        for (int ks = 0; ks < 2; ks++) {
            wmma::fragment<wmma::matrix_a, 16, 16, 8, wmma::precision::tf32, wmma::row_major> af[4];
#pragma unroll
            for (int mt = 0; mt < 4; mt++) {
                wmma::load_matrix_sync(af[mt], &As[cur][wm * 64 + mt * 16][ks * 8], GBK + 4);
#pragma unroll
                for (int t = 0; t < af[mt].num_elements; t++)
                    af[mt].x[t] = wmma::__float_to_tf32(af[mt].x[t]);
            }
#pragma unroll
            for (int nt = 0; nt < 2; nt++) {
                wmma::fragment<wmma::matrix_b, 16, 16, 8, wmma::precision::tf32, wmma::row_major> bf;
                wmma::load_matrix_sync(bf, &Bs[cur][ks * 8][wn * 32 + nt * 16], GBN);
#pragma unroll
                for (int t = 0; t < bf.num_elements; t++)
                    bf.x[t] = wmma::__float_to_tf32(bf.x[t]);
#pragma unroll
                for (int mt = 0; mt < 4; mt++)
                    wmma::mma_sync(acc[mt][nt], af[mt], bf, acc[mt][nt]);
            }
        }

        if (it + 1 < NIT) {
            const int nxt = 1 - cur;
#pragma unroll
            for (int i = 0; i < 2; i++) {
                *reinterpret_cast<float4*>(&As[nxt][ar0 + i * 64][ac]) = a_reg[i];
                *reinterpret_cast<float4*>(&Bs[nxt][br0 + i * 8][bc]) = b_reg[i];
            }
            __syncthreads();
        }
    }

#pragma unroll
    for (int mt = 0; mt < 4; mt++)
#pragma unroll
        for (int nt = 0; nt < 2; nt++)
            wmma::store_matrix_sync(
                h + (size_t)(row0 + wm * 64 + mt * 16) * OUT_F + wn * 32 + nt * 16,
                acc[mt][nt], OUT_F, wmma::mem_row_major);
}

// ---------------- per-node scores + fp16 mirror of h --------------------------
__global__ __launch_bounds__(256) void score_kernel(
    const float* __restrict__ h, const float* __restrict__ a,
    float* __restrict__ ssrc, float* __restrict__ sdst,
    __half* __restrict__ hh, int N)
{
    const int warp = (blockIdx.x * blockDim.x + threadIdx.x) >> 5;
    const int lane = threadIdx.x & 31;
    if (warp >= N) return;

    const float4 hv = reinterpret_cast<const float4*>(h + (size_t)warp * OUT_F)[lane];
    const float4 as = reinterpret_cast<const float4*>(a)[lane];
    const float4 ad = reinterpret_cast<const float4*>(a + OUT_F)[lane];

    __half2 p0 = __floats2half2_rn(hv.x, hv.y);
    __half2 p1 = __floats2half2_rn(hv.z, hv.w);
    reinterpret_cast<__half2*>(hh + (size_t)warp * OUT_F)[lane * 2]     = p0;
    reinterpret_cast<__half2*>(hh + (size_t)warp * OUT_F)[lane * 2 + 1] = p1;

    float s1 = hv.x * as.x + hv.y * as.y + hv.z * as.z + hv.w * as.w;
    float s2 = hv.x * ad.x + hv.y * ad.y + hv.z * ad.z + hv.w * ad.w;
#pragma unroll
    for (int o = 16; o > 0; o >>= 1) {
        s1 += __shfl_xor_sync(0xFFFFFFFFu, s1, o);
        s2 += __shfl_xor_sync(0xFFFFFFFFu, s2, o);
    }
    if (lane == 0) { ssrc[warp] = s1; sdst[warp] = s2; }
}

// ---------------- CSR build: histogram --------------------------------------
__global__ __launch_bounds__(256) void hist_kernel(
    const int* __restrict__ src, int* __restrict__ deg, int E)
{
    const int e = blockIdx.x * blockDim.x + threadIdx.x;
    if (e < E) atomicAdd(&deg[src[e]], 1);
}

// ---------------- scan phase 1: per-block sums --------------------------------
__global__ __launch_bounds__(SCAN_BS) void scan1_kernel(
    const int* __restrict__ deg, int* __restrict__ part, int N)
{
    __shared__ int sh[SCAN_BS];
    const int idx = blockIdx.x * SCAN_BS + threadIdx.x;
    int v = (idx < N) ? deg[idx] : 0;
    sh[threadIdx.x] = v;
    __syncthreads();
#pragma unroll
    for (int o = SCAN_BS / 2; o > 0; o >>= 1) {
        if (threadIdx.x < o) sh[threadIdx.x] += sh[threadIdx.x + o];
        __syncthreads();
    }
    if (threadIdx.x == 0) part[blockIdx.x] = sh[0];
}

// ---------------- scan phase 2: exclusive scan of partials (1 block) ----------
__global__ __launch_bounds__(SCAN_BS) void scan2_kernel(int* __restrict__ part)
{
    __shared__ int sh[SCAN_BS];
    const int t = threadIdx.x;
    int v = (t < SCAN_NB) ? part[t] : 0;
    sh[t] = v;
    __syncthreads();
#pragma unroll
    for (int o = 1; o < SCAN_BS; o <<= 1) {
        int u = (t >= o) ? sh[t - o] : 0;
        __syncthreads();
        sh[t] += u;
        __syncthreads();
    }
    if (t < SCAN_NB) part[t] = sh[t] - v;
}

// ---------------- scan phase 3: local scan + write offsets --------------------
__global__ __launch_bounds__(SCAN_BS) void scan3_kernel(
    const int* __restrict__ deg, const int* __restrict__ part,
    int* __restrict__ off, int* __restrict__ cursor, int N, int E)
{
    __shared__ int sh[SCAN_BS];
    const int t = threadIdx.x;
    const int idx = blockIdx.x * SCAN_BS + t;
    int v = (idx < N) ? deg[idx] : 0;
    sh[t] = v;
    __syncthreads();
#pragma unroll
    for (int o = 1; o < SCAN_BS; o <<= 1) {
        int u = (t >= o) ? sh[t - o] : 0;
        __syncthreads();
        sh[t] += u;
        __syncthreads();
    }
    if (idx < N) {
        const int o = part[blockIdx.x] + sh[t] - v;
        off[idx] = o;
        cursor[idx] = o;
        if (idx == N - 1) off[N] = E;
    }
}

// ---------------- CSR build: scatter + edge weights (packed int2) -------------
__global__ __launch_bounds__(256) void scatter_kernel(
    const int* __restrict__ src, const int* __restrict__ dst,
    const float* __restrict__ ssrc, const float* __restrict__ sdst,
    int* __restrict__ cursor, int2* __restrict__ edge, int E)
{
    const int e = blockIdx.x * blockDim.x + threadIdx.x;
    if (e >= E) return;
    const int s = src[e];
    const int d = dst[e];
    const float sc = ssrc[s] + sdst[d];
    const float lr = sc >= 0.f ? sc : ALPHA * sc;
    const float w = __expf(-lr);
    const int pos = atomicAdd(&cursor[s], 1);
    edge[pos] = make_int2(d, __float_as_int(w));
}

// ---------------- aggregate: warp/node, double-buffered edges, fused elu ------
__global__ __launch_bounds__(256) void aggregate_kernel(
    const uint2* __restrict__ hh2, const int* __restrict__ off,
    const uint2* __restrict__ edge, float4* __restrict__ out4, int N)
{
    const int warp = (blockIdx.x * blockDim.x + threadIdx.x) >> 5;
    const int lane = threadIdx.x & 31;
    if (warp >= N) return;

    const int beg = off[warp];
    const int end = off[warp + 1];

    float ax = 0.f, ay = 0.f, az = 0.f, aw = 0.f, wsum = 0.f;

    const int nb = (end - beg) >> 3;       // full batches of 8
    uint2 eb[2][8];
    if (nb > 0) {
#pragma unroll
        for (int j = 0; j < 8; j++) eb[0][j] = edge[beg + j];
    }
    for (int b = 0; b < nb; b++) {
        const int cur = b & 1;
        if (b + 1 < nb) {
            const int base = beg + (b + 1) * 8;
#pragma unroll
            for (int j = 0; j < 8; j++) eb[1 - cur][j] = edge[base + j];
        }
        uint2 u[8];
#pragma unroll
        for (int j = 0; j < 8; j++) u[j] = hh2[(size_t)eb[cur][j].x * 32 + lane];
#pragma unroll
        for (int j = 0; j < 8; j++) {
            const float w = __int_as_float((int)eb[cur][j].y);
            float2 lo = __half22float2(*(const __half2*)&u[j].x);
            float2 hi = __half22float2(*(const __half2*)&u[j].y);
            ax = fmaf(w, lo.x, ax);
            ay = fmaf(w, lo.y, ay);
            az = fmaf(w, hi.x, az);
            aw = fmaf(w, hi.y, aw);
            wsum += w;
        }
    }
    for (int i = beg + nb * 8; i < end; i++) {
        const uint2 ed = edge[i];
        const float w = __int_as_float((int)ed.y);
        const uint2 u = hh2[(size_t)ed.x * 32 + lane];
        float2 lo = __half22float2(*(const __half2*)&u.x);
        float2 hi = __half22float2(*(const __half2*)&u.y);
        ax = fmaf(w, lo.x, ax);
        ay = fmaf(w, lo.y, ay);
        az = fmaf(w, hi.x, az);
        aw = fmaf(w, hi.y, aw);
        wsum += w;
    }

    const float r = 1.f / (wsum + EPSV);
    ax *= r; ay *= r; az *= r; aw *= r;
    ax = ax > 0.f ? ax : expm1f(ax);
    ay = ay > 0.f ? ay : expm1f(ay);
    az = az > 0.f ? az : expm1f(az);
    aw = aw > 0.f ? aw : expm1f(aw);
    out4[(size_t)warp * 32 + lane] = make_float4(ax, ay, az, aw);
}

// ---------------- launch ------------------------------------------------------
extern "C" void kernel_launch(void* const* d_in, const int* in_sizes, int n_in,
                              void* d_out, int out_size)
{
    const float* x  = (const float*)d_in[0];
    const int*   ei = (const int*)d_in[1];      // JAX x64 disabled -> int32
    const float* W  = (const float*)d_in[2];
    const float* a  = (const float*)d_in[3];
    float* out = (float*)d_out;

    const int N = in_sizes[0] / IN_F;        // 50000
    const int E = in_sizes[1] / 2;           // 1600000
    const int* src = ei;
    const int* dst = ei + E;

    float *h, *ssrc, *sdst;
    __half* hh;
    int *deg, *off, *cursor, *part;
    int2* edge;
    cudaGetSymbolAddress((void**)&h,      g_h);
    cudaGetSymbolAddress((void**)&hh,     g_hh);
    cudaGetSymbolAddress((void**)&ssrc,   g_ssrc);
    cudaGetSymbolAddress((void**)&sdst,   g_sdst);
    cudaGetSymbolAddress((void**)&deg,    g_deg);
    cudaGetSymbolAddress((void**)&off,    g_off);
    cudaGetSymbolAddress((void**)&cursor, g_cursor);
    cudaGetSymbolAddress((void**)&part,   g_part);
    cudaGetSymbolAddress((void**)&edge,   g_edge);

    cudaMemsetAsync(deg, 0, (size_t)N_NODES * sizeof(int), 0);

    // CSR histogram
    hist_kernel<<<(E + 255) / 256, 256>>>(src, deg, E);

    // 3-phase parallel exclusive scan
    scan1_kernel<<<SCAN_NB, SCAN_BS>>>(deg, part, N);
    scan2_kernel<<<1, SCAN_BS>>>(part);
    scan3_kernel<<<SCAN_NB, SCAN_BS>>>(deg, part, off, cursor, N, E);

    // h = x @ W (tf32 tensor cores, double-buffered)
    gemm_tf32_kernel<<<(N + GBM - 1) / GBM, 256>>>(x, W, h, N);

    // per-node scores + fp16 mirror
    score_kernel<<<(N + 7) / 8, 256>>>(h, a, ssrc, sdst, hh, N);

    // scatter edges into CSR order + precompute weights (packed)
    scatter_kernel<<<(E + 255) / 256, 256>>>(src, dst, ssrc, sdst, cursor, edge, E);

    // aggregate per node (atomic-free, fp16 gather, double-buffered) + fused elu
    aggregate_kernel<<<(N * 32 + 255) / 256, 256>>>(
        (const uint2*)hh, off, (const uint2*)edge, (float4*)out, N);
}

// round 14
// speedup vs baseline: 1.1636x; 1.1636x over previous
#include <cuda_runtime.h>
#include <cuda_fp16.h>
#include <cuda_bf16.h>
#include <mma.h>
#include <math.h>

using namespace nvcuda;

#define N_NODES 50000
#define N_EDGES 1600000
#define IN_F    256
#define OUT_F   128
#define ALPHA   0.2f
#define EPSV    1e-9f

// GEMM tiling: 128x128 block tile, BK=16, double-buffered smem
#define GBM 128
#define GBN 128
#define GBK 16
#define N_PAD 50048   // 391 blocks * 128 rows

// scan config
#define SCAN_BS 256
#define SCAN_NB ((N_NODES + SCAN_BS - 1) / SCAN_BS)   // 196

// ---------------- scratch (device globals; no allocations allowed) ----------
__device__ float  g_h[(size_t)N_PAD * OUT_F];
__device__ __half g_hh[(size_t)N_NODES * OUT_F];
__device__ float  g_ssrc[N_NODES];
__device__ float  g_sdst[N_NODES];
__device__ int    g_deg[N_NODES];
__device__ int    g_off[N_NODES + 1];
__device__ int    g_cursor[N_NODES];
__device__ int    g_part[SCAN_NB];
__device__ int2   g_edge[N_EDGES];    // packed (dst, w bits)

// ---------------- GEMM: h = x @ W  (tf32, double-buffered) ------------------
__global__ __launch_bounds__(256) void gemm_tf32_kernel(
    const float* __restrict__ x, const float* __restrict__ W,
    float* __restrict__ h, int N)
{
    __shared__ float As[2][GBM][GBK + 4];
    __shared__ float Bs[2][GBK][GBN];

    const int tid = threadIdx.x;
    const int wid = tid >> 5;
    const int wm = wid >> 2;
    const int wn = wid & 3;
    const int row0 = blockIdx.x * GBM;

    const int ar0 = tid >> 2;
    const int ac  = (tid & 3) * 4;
    const int br0 = tid >> 5;
    const int bc  = (tid & 31) * 4;

    wmma::fragment<wmma::accumulator, 16, 16, 8, float> acc[4][2];
#pragma unroll
    for (int i = 0; i < 4; i++)
#pragma unroll
        for (int j = 0; j < 2; j++) wmma::fill_fragment(acc[i][j], 0.f);

#pragma unroll
    for (int i = 0; i < 2; i++) {
        int grow = row0 + ar0 + i * 64; if (grow >= N) grow = N - 1;
        *reinterpret_cast<float4*>(&As[0][ar0 + i * 64][ac]) =
            *reinterpret_cast<const float4*>(x + (size_t)grow * IN_F + ac);
        *reinterpret_cast<float4*>(&Bs[0][br0 + i * 8][bc]) =
            *reinterpret_cast<const float4*>(W + (size_t)(br0 + i * 8) * GBN + bc);
    }
    __syncthreads();

    const int NIT = IN_F / GBK;   // 16
    for (int it = 0; it < NIT; it++) {
        const int cur = it & 1;
        float4 a_reg[2], b_reg[2];
        if (it + 1 < NIT) {
            const int k0 = (it + 1) * GBK;
#pragma unroll
            for (int i = 0; i < 2; i++) {
                int grow = row0 + ar0 + i * 64; if (grow >= N) grow = N - 1;
                a_reg[i] = *reinterpret_cast<const float4*>(x + (size_t)grow * IN_F + k0 + ac);
                b_reg[i] = *reinterpret_cast<const float4*>(W + (size_t)(k0 + br0 + i * 8) * GBN + bc);
            }
        }

#pragma unroll
        for (int ks = 0; ks < 2; ks++) {
            wmma::fragment<wmma::matrix_a, 16, 16, 8, wmma::precision::tf32, wmma::row_major> af[4];
#pragma unroll
            for (int mt = 0; mt < 4; mt++) {
                wmma::load_matrix_sync(af[mt], &As[cur][wm * 64 + mt * 16][ks * 8], GBK + 4);
#pragma unroll
                for (int t = 0; t < af[mt].num_elements; t++)
                    af[mt].x[t] = wmma::__float_to_tf32(af[mt].x[t]);
            }
#pragma unroll
            for (int nt = 0; nt < 2; nt++) {
                wmma::fragment<wmma::matrix_b, 16, 16, 8, wmma::precision::tf32, wmma::row_major> bf;
                wmma::load_matrix_sync(bf, &Bs[cur][ks * 8][wn * 32 + nt * 16], GBN);
#pragma unroll
                for (int t = 0; t < bf.num_elements; t++)
                    bf.x[t] = wmma::__float_to_tf32(bf.x[t]);
#pragma unroll
                for (int mt = 0; mt < 4; mt++)
                    wmma::mma_sync(acc[mt][nt], af[mt], bf, acc[mt][nt]);
            }
        }

        if (it + 1 < NIT) {
            const int nxt = 1 - cur;
#pragma unroll
            for (int i = 0; i < 2; i++) {
                *reinterpret_cast<float4*>(&As[nxt][ar0 + i * 64][ac]) = a_reg[i];
                *reinterpret_cast<float4*>(&Bs[nxt][br0 + i * 8][bc]) = b_reg[i];
            }
            __syncthreads();
        }
    }

#pragma unroll
    for (int mt = 0; mt < 4; mt++)
#pragma unroll
        for (int nt = 0; nt < 2; nt++)
            wmma::store_matrix_sync(
                h + (size_t)(row0 + wm * 64 + mt * 16) * OUT_F + wn * 32 + nt * 16,
                acc[mt][nt], OUT_F, wmma::mem_row_major);
}

// ---------------- per-node scores + fp16 mirror of h --------------------------
__global__ __launch_bounds__(256) void score_kernel(
    const float* __restrict__ h, const float* __restrict__ a,
    float* __restrict__ ssrc, float* __restrict__ sdst,
    __half* __restrict__ hh, int N)
{
    const int warp = (blockIdx.x * blockDim.x + threadIdx.x) >> 5;
    const int lane = threadIdx.x & 31;
    if (warp >= N) return;

    const float4 hv = reinterpret_cast<const float4*>(h + (size_t)warp * OUT_F)[lane];
    const float4 as = reinterpret_cast<const float4*>(a)[lane];
    const float4 ad = reinterpret_cast<const float4*>(a + OUT_F)[lane];

    __half2 p0 = __floats2half2_rn(hv.x, hv.y);
    __half2 p1 = __floats2half2_rn(hv.z, hv.w);
    reinterpret_cast<__half2*>(hh + (size_t)warp * OUT_F)[lane * 2]     = p0;
    reinterpret_cast<__half2*>(hh + (size_t)warp * OUT_F)[lane * 2 + 1] = p1;

    float s1 = hv.x * as.x + hv.y * as.y + hv.z * as.z + hv.w * as.w;
    float s2 = hv.x * ad.x + hv.y * ad.y + hv.z * ad.z + hv.w * ad.w;
#pragma unroll
    for (int o = 16; o > 0; o >>= 1) {
        s1 += __shfl_xor_sync(0xFFFFFFFFu, s1, o);
        s2 += __shfl_xor_sync(0xFFFFFFFFu, s2, o);
    }
    if (lane == 0) { ssrc[warp] = s1; sdst[warp] = s2; }
}

// ---------------- CSR build: histogram --------------------------------------
__global__ __launch_bounds__(256) void hist_kernel(
    const int* __restrict__ src, int* __restrict__ deg, int E)
{
    const int e = blockIdx.x * blockDim.x + threadIdx.x;
    if (e < E) atomicAdd(&deg[src[e]], 1);
}

// ---------------- scan phase 1: per-block sums --------------------------------
__global__ __launch_bounds__(SCAN_BS) void scan1_kernel(
    const int* __restrict__ deg, int* __restrict__ part, int N)
{
    __shared__ int sh[SCAN_BS];
    const int idx = blockIdx.x * SCAN_BS + threadIdx.x;
    int v = (idx < N) ? deg[idx] : 0;
    sh[threadIdx.x] = v;
    __syncthreads();
#pragma unroll
    for (int o = SCAN_BS / 2; o > 0; o >>= 1) {
        if (threadIdx.x < o) sh[threadIdx.x] += sh[threadIdx.x + o];
        __syncthreads();
    }
    if (threadIdx.x == 0) part[blockIdx.x] = sh[0];
}

// ---------------- scan phase 2: exclusive scan of partials (1 block) ----------
__global__ __launch_bounds__(SCAN_BS) void scan2_kernel(int* __restrict__ part)
{
    __shared__ int sh[SCAN_BS];
    const int t = threadIdx.x;
    int v = (t < SCAN_NB) ? part[t] : 0;
    sh[t] = v;
    __syncthreads();
#pragma unroll
    for (int o = 1; o < SCAN_BS; o <<= 1) {
        int u = (t >= o) ? sh[t - o] : 0;
        __syncthreads();
        sh[t] += u;
        __syncthreads();
    }
    if (t < SCAN_NB) part[t] = sh[t] - v;
}

// ---------------- scan phase 3: local scan + write offsets --------------------
__global__ __launch_bounds__(SCAN_BS) void scan3_kernel(
    const int* __restrict__ deg, const int* __restrict__ part,
    int* __restrict__ off, int* __restrict__ cursor, int N, int E)
{
    __shared__ int sh[SCAN_BS];
    const int t = threadIdx.x;
    const int idx = blockIdx.x * SCAN_BS + t;
    int v = (idx < N) ? deg[idx] : 0;
    sh[t] = v;
    __syncthreads();
#pragma unroll
    for (int o = 1; o < SCAN_BS; o <<= 1) {
        int u = (t >= o) ? sh[t - o] : 0;
        __syncthreads();
        sh[t] += u;
        __syncthreads();
    }
    if (idx < N) {
        const int o = part[blockIdx.x] + sh[t] - v;
        off[idx] = o;
        cursor[idx] = o;
        if (idx == N - 1) off[N] = E;
    }
}

// ---------------- CSR build: scatter + edge weights (packed int2) -------------
__global__ __launch_bounds__(256) void scatter_kernel(
    const int* __restrict__ src, const int* __restrict__ dst,
    const float* __restrict__ ssrc, const float* __restrict__ sdst,
    int* __restrict__ cursor, int2* __restrict__ edge, int E)
{
    const int e = blockIdx.x * blockDim.x + threadIdx.x;
    if (e >= E) return;
    const int s = src[e];
    const int d = dst[e];
    const float sc = ssrc[s] + sdst[d];
    const float lr = sc >= 0.f ? sc : ALPHA * sc;
    const float w = __expf(-lr);
    const int pos = atomicAdd(&cursor[s], 1);
    edge[pos] = make_int2(d, __float_as_int(w));
}

// ---------------- aggregate: 2 nodes/warp, 16 lanes/node, unroll 8 ------------
// Each lane owns 8 features (uint4 = 8 fp16). 16 outstanding gathers per warp.
__global__ __launch_bounds__(512) void aggregate_kernel(
    const uint4* __restrict__ hh4, const int* __restrict__ off,
    const uint2* __restrict__ edge, float4* __restrict__ out4, int N)
{
    const int warp = (blockIdx.x * blockDim.x + threadIdx.x) >> 5;
    const int half = (threadIdx.x >> 4) & 1;
    const int sub  = threadIdx.x & 15;
    const int node = warp * 2 + half;
    if (node >= N) return;

    const int beg = off[node];
    const int end = off[node + 1];

    float a0 = 0.f, a1 = 0.f, a2 = 0.f, a3 = 0.f;
    float a4 = 0.f, a5 = 0.f, a6 = 0.f, a7 = 0.f;
    float wsum = 0.f;

    int i = beg;
    for (; i + 8 <= end; i += 8) {
        uint2 ed[8]; uint4 u[8];
#pragma unroll
        for (int j = 0; j < 8; j++) ed[j] = edge[i + j];
#pragma unroll
        for (int j = 0; j < 8; j++) u[j] = hh4[(size_t)ed[j].x * 16 + sub];
#pragma unroll
        for (int j = 0; j < 8; j++) {
            const float w = __int_as_float((int)ed[j].y);
            const float2 f0 = __half22float2(*(const __half2*)&u[j].x);
            const float2 f1 = __half22float2(*(const __half2*)&u[j].y);
            const float2 f2 = __half22float2(*(const __half2*)&u[j].z);
            const float2 f3 = __half22float2(*(const __half2*)&u[j].w);
            a0 = fmaf(w, f0.x, a0); a1 = fmaf(w, f0.y, a1);
            a2 = fmaf(w, f1.x, a2); a3 = fmaf(w, f1.y, a3);
            a4 = fmaf(w, f2.x, a4); a5 = fmaf(w, f2.y, a5);
            a6 = fmaf(w, f3.x, a6); a7 = fmaf(w, f3.y, a7);
            wsum += w;
        }
    }
    for (; i < end; i++) {
        const uint2 ed = edge[i];
        const float w = __int_as_float((int)ed.y);
        const uint4 u = hh4[(size_t)ed.x * 16 + sub];
        const float2 f0 = __half22float2(*(const __half2*)&u.x);
        const float2 f1 = __half22float2(*(const __half2*)&u.y);
        const float2 f2 = __half22float2(*(const __half2*)&u.z);
        const float2 f3 = __half22float2(*(const __half2*)&u.w);
        a0 = fmaf(w, f0.x, a0); a1 = fmaf(w, f0.y, a1);
        a2 = fmaf(w, f1.x, a2); a3 = fmaf(w, f1.y, a3);
        a4 = fmaf(w, f2.x, a4); a5 = fmaf(w, f2.y, a5);
        a6 = fmaf(w, f3.x, a6); a7 = fmaf(w, f3.y, a7);
        wsum += w;
    }

    const float r = 1.f / (wsum + EPSV);
    a0 *= r; a1 *= r; a2 *= r; a3 *= r;
    a4 *= r; a5 *= r; a6 *= r; a7 *= r;
    a0 = a0 > 0.f ? a0 : expm1f(a0);
    a1 = a1 > 0.f ? a1 : expm1f(a1);
    a2 = a2 > 0.f ? a2 : expm1f(a2);
    a3 = a3 > 0.f ? a3 : expm1f(a3);
    a4 = a4 > 0.f ? a4 : expm1f(a4);
    a5 = a5 > 0.f ? a5 : expm1f(a5);
    a6 = a6 > 0.f ? a6 : expm1f(a6);
    a7 = a7 > 0.f ? a7 : expm1f(a7);

    out4[(size_t)node * 32 + sub * 2]     = make_float4(a0, a1, a2, a3);
    out4[(size_t)node * 32 + sub * 2 + 1] = make_float4(a4, a5, a6, a7);
}

// ---------------- launch ------------------------------------------------------
extern "C" void kernel_launch(void* const* d_in, const int* in_sizes, int n_in,
                              void* d_out, int out_size)
{
    const float* x  = (const float*)d_in[0];
    const int*   ei = (const int*)d_in[1];      // JAX x64 disabled -> int32
    const float* W  = (const float*)d_in[2];
    const float* a  = (const float*)d_in[3];
    float* out = (float*)d_out;

    const int N = in_sizes[0] / IN_F;        // 50000
    const int E = in_sizes[1] / 2;           // 1600000
    const int* src = ei;
    const int* dst = ei + E;

    float *h, *ssrc, *sdst;
    __half* hh;
    int *deg, *off, *cursor, *part;
    int2* edge;
    cudaGetSymbolAddress((void**)&h,      g_h);
    cudaGetSymbolAddress((void**)&hh,     g_hh);
    cudaGetSymbolAddress((void**)&ssrc,   g_ssrc);
    cudaGetSymbolAddress((void**)&sdst,   g_sdst);
    cudaGetSymbolAddress((void**)&deg,    g_deg);
    cudaGetSymbolAddress((void**)&off,    g_off);
    cudaGetSymbolAddress((void**)&cursor, g_cursor);
    cudaGetSymbolAddress((void**)&part,   g_part);
    cudaGetSymbolAddress((void**)&edge,   g_edge);

    cudaMemsetAsync(deg, 0, (size_t)N_NODES * sizeof(int), 0);

    // CSR histogram
    hist_kernel<<<(E + 255) / 256, 256>>>(src, deg, E);

    // 3-phase parallel exclusive scan
    scan1_kernel<<<SCAN_NB, SCAN_BS>>>(deg, part, N);
    scan2_kernel<<<1, SCAN_BS>>>(part);
    scan3_kernel<<<SCAN_NB, SCAN_BS>>>(deg, part, off, cursor, N, E);

    // h = x @ W (tf32 tensor cores, double-buffered)
    gemm_tf32_kernel<<<(N + GBM - 1) / GBM, 256>>>(x, W, h, N);

    // per-node scores + fp16 mirror
    score_kernel<<<(N + 7) / 8, 256>>>(h, a, ssrc, sdst, hh, N);

    // scatter edges into CSR order + precompute weights (packed)
    scatter_kernel<<<(E + 255) / 256, 256>>>(src, dst, ssrc, sdst, cursor, edge, E);

    // aggregate: 2 nodes per warp, 16 lanes/node (atomic-free) + fused elu
    {
        const int warps = (N + 1) / 2;
        const int blocks = (warps * 32 + 511) / 512;
        aggregate_kernel<<<blocks, 512>>>(
            (const uint4*)hh, off, (const uint2*)edge, (float4*)out, N);
    }
}

// round 15
// speedup vs baseline: 1.1775x; 1.0119x over previous
#include <cuda_runtime.h>
#include <cuda_fp16.h>
#include <cuda_bf16.h>
#include <mma.h>
#include <math.h>

using namespace nvcuda;

#define N_NODES 50000
#define N_EDGES 1600000
#define IN_F    256
#define OUT_F   128
#define ALPHA   0.2f
#define EPSV    1e-9f

// GEMM tiling: 128x128 block tile, BK=16, double-buffered smem
#define GBM 128
#define GBN 128
#define GBK 16
#define N_PAD 50048   // 391 blocks * 128 rows

// scan config
#define SCAN_BS 256
#define SCAN_NB ((N_NODES + SCAN_BS - 1) / SCAN_BS)   // 196

// ---------------- scratch (device globals; no allocations allowed) ----------
__device__ float  g_h[(size_t)N_PAD * OUT_F];
__device__ __half g_hh[(size_t)N_NODES * OUT_F];
__device__ float  g_ssrc[N_NODES];
__device__ float  g_sdst[N_NODES];
__device__ int    g_deg[N_NODES];
__device__ int    g_off[N_NODES + 1];
__device__ int    g_cursor[N_NODES];
__device__ int    g_part[SCAN_NB];
__device__ int2   g_edge[N_EDGES];    // packed (dst, w bits)

// ---------------- GEMM: h = x @ W  (tf32, double-buffered) ------------------
__global__ __launch_bounds__(256) void gemm_tf32_kernel(
    const float* __restrict__ x, const float* __restrict__ W,
    float* __restrict__ h, int N)
{
    __shared__ float As[2][GBM][GBK + 4];
    __shared__ float Bs[2][GBK][GBN];

    const int tid = threadIdx.x;
    const int wid = tid >> 5;
    const int wm = wid >> 2;
    const int wn = wid & 3;
    const int row0 = blockIdx.x * GBM;

    const int ar0 = tid >> 2;
    const int ac  = (tid & 3) * 4;
    const int br0 = tid >> 5;
    const int bc  = (tid & 31) * 4;

    wmma::fragment<wmma::accumulator, 16, 16, 8, float> acc[4][2];
#pragma unroll
    for (int i = 0; i < 4; i++)
#pragma unroll
        for (int j = 0; j < 2; j++) wmma::fill_fragment(acc[i][j], 0.f);

#pragma unroll
    for (int i = 0; i < 2; i++) {
        int grow = row0 + ar0 + i * 64; if (grow >= N) grow = N - 1;
        *reinterpret_cast<float4*>(&As[0][ar0 + i * 64][ac]) =
            *reinterpret_cast<const float4*>(x + (size_t)grow * IN_F + ac);
        *reinterpret_cast<float4*>(&Bs[0][br0 + i * 8][bc]) =
            *reinterpret_cast<const float4*>(W + (size_t)(br0 + i * 8) * GBN + bc);
    }
    __syncthreads();

    const int NIT = IN_F / GBK;   // 16
    for (int it = 0; it < NIT; it++) {
        const int cur = it & 1;
        float4 a_reg[2], b_reg[2];
        if (it + 1 < NIT) {
            const int k0 = (it + 1) * GBK;
#pragma unroll
            for (int i = 0; i < 2; i++) {
                int grow = row0 + ar0 + i * 64; if (grow >= N) grow = N - 1;
                a_reg[i] = *reinterpret_cast<const float4*>(x + (size_t)grow * IN_F + k0 + ac);
                b_reg[i] = *reinterpret_cast<const float4*>(W + (size_t)(k0 + br0 + i * 8) * GBN + bc);
            }
        }

#pragma unroll
        for (int ks = 0; ks < 2; ks++) {
            wmma::fragment<wmma::matrix_a, 16, 16, 8, wmma::precision::tf32, wmma::row_major> af[4];
#pragma unroll
            for (int mt = 0; mt < 4; mt++) {
                wmma::load_matrix_sync(af[mt], &As[cur][wm * 64 + mt * 16][ks * 8], GBK + 4);
#pragma unroll
                for (int t = 0; t < af[mt].num_elements; t++)
                    af[mt].x[t] = wmma::__float_to_tf32(af[mt].x[t]);
            }
#pragma unroll
            for (int nt = 0; nt < 2; nt++) {
                wmma::fragment<wmma::matrix_b, 16, 16, 8, wmma::precision::tf32, wmma::row_major> bf;
                wmma::load_matrix_sync(bf, &Bs[cur][ks * 8][wn * 32 + nt * 16], GBN);
#pragma unroll
                for (int t = 0; t < bf.num_elements; t++)
                    bf.x[t] = wmma::__float_to_tf32(bf.x[t]);
#pragma unroll
                for (int mt = 0; mt < 4; mt++)
                    wmma::mma_sync(acc[mt][nt], af[mt], bf, acc[mt][nt]);
            }
        }

        if (it + 1 < NIT) {
            const int nxt = 1 - cur;
#pragma unroll
            for (int i = 0; i < 2; i++) {
                *reinterpret_cast<float4*>(&As[nxt][ar0 + i * 64][ac]) = a_reg[i];
                *reinterpret_cast<float4*>(&Bs[nxt][br0 + i * 8][bc]) = b_reg[i];
            }
            __syncthreads();
        }
    }

#pragma unroll
    for (int mt = 0; mt < 4; mt++)
#pragma unroll
        for (int nt = 0; nt < 2; nt++)
            wmma::store_matrix_sync(
                h + (size_t)(row0 + wm * 64 + mt * 16) * OUT_F + wn * 32 + nt * 16,
                acc[mt][nt], OUT_F, wmma::mem_row_major);
}

// ---------------- per-node scores + fp16 mirror of h --------------------------
__global__ __launch_bounds__(256) void score_kernel(
    const float* __restrict__ h, const float* __restrict__ a,
    float* __restrict__ ssrc, float* __restrict__ sdst,
    __half* __restrict__ hh, int N)
{
    const int warp = (blockIdx.x * blockDim.x + threadIdx.x) >> 5;
    const int lane = threadIdx.x & 31;
    if (warp >= N) return;

    const float4 hv = reinterpret_cast<const float4*>(h + (size_t)warp * OUT_F)[lane];
    const float4 as = reinterpret_cast<const float4*>(a)[lane];
    const float4 ad = reinterpret_cast<const float4*>(a + OUT_F)[lane];

    __half2 p0 = __floats2half2_rn(hv.x, hv.y);
    __half2 p1 = __floats2half2_rn(hv.z, hv.w);
    reinterpret_cast<__half2*>(hh + (size_t)warp * OUT_F)[lane * 2]     = p0;
    reinterpret_cast<__half2*>(hh + (size_t)warp * OUT_F)[lane * 2 + 1] = p1;

    float s1 = hv.x * as.x + hv.y * as.y + hv.z * as.z + hv.w * as.w;
    float s2 = hv.x * ad.x + hv.y * ad.y + hv.z * ad.z + hv.w * ad.w;
#pragma unroll
    for (int o = 16; o > 0; o >>= 1) {
        s1 += __shfl_xor_sync(0xFFFFFFFFu, s1, o);
        s2 += __shfl_xor_sync(0xFFFFFFFFu, s2, o);
    }
    if (lane == 0) { ssrc[warp] = s1; sdst[warp] = s2; }
}

// ---------------- CSR build: histogram --------------------------------------
__global__ __launch_bounds__(256) void hist_kernel(
    const int* __restrict__ src, int* __restrict__ deg, int E)
{
    const int e = blockIdx.x * blockDim.x + threadIdx.x;
    if (e < E) atomicAdd(&deg[src[e]], 1);
}

// ---------------- scan phase 1: per-block sums --------------------------------
__global__ __launch_bounds__(SCAN_BS) void scan1_kernel(
    const int* __restrict__ deg, int* __restrict__ part, int N)
{
    __shared__ int sh[SCAN_BS];
    const int idx = blockIdx.x * SCAN_BS + threadIdx.x;
    int v = (idx < N) ? deg[idx] : 0;
    sh[threadIdx.x] = v;
    __syncthreads();
#pragma unroll
    for (int o = SCAN_BS / 2; o > 0; o >>= 1) {
        if (threadIdx.x < o) sh[threadIdx.x] += sh[threadIdx.x + o];
        __syncthreads();
    }
    if (threadIdx.x == 0) part[blockIdx.x] = sh[0];
}

// ---------------- scan phase 2: exclusive scan of partials (1 block) ----------
__global__ __launch_bounds__(SCAN_BS) void scan2_kernel(int* __restrict__ part)
{
    __shared__ int sh[SCAN_BS];
    const int t = threadIdx.x;
    int v = (t < SCAN_NB) ? part[t] : 0;
    sh[t] = v;
    __syncthreads();
#pragma unroll
    for (int o = 1; o < SCAN_BS; o <<= 1) {
        int u = (t >= o) ? sh[t - o] : 0;
        __syncthreads();
        sh[t] += u;
        __syncthreads();
    }
    if (t < SCAN_NB) part[t] = sh[t] - v;
}

// ---------------- scan phase 3: local scan + write offsets --------------------
__global__ __launch_bounds__(SCAN_BS) void scan3_kernel(
    const int* __restrict__ deg, const int* __restrict__ part,
    int* __restrict__ off, int* __restrict__ cursor, int N, int E)
{
    __shared__ int sh[SCAN_BS];
    const int t = threadIdx.x;
    const int idx = blockIdx.x * SCAN_BS + t;
    int v = (idx < N) ? deg[idx] : 0;
    sh[t] = v;
    __syncthreads();
#pragma unroll
    for (int o = 1; o < SCAN_BS; o <<= 1) {
        int u = (t >= o) ? sh[t - o] : 0;
        __syncthreads();
        sh[t] += u;
        __syncthreads();
    }
    if (idx < N) {
        const int o = part[blockIdx.x] + sh[t] - v;
        off[idx] = o;
        cursor[idx] = o;
        if (idx == N - 1) off[N] = E;
    }
}

// ---------------- CSR build: scatter + edge weights (packed int2) -------------
__global__ __launch_bounds__(256) void scatter_kernel(
    const int* __restrict__ src, const int* __restrict__ dst,
    const float* __restrict__ ssrc, const float* __restrict__ sdst,
    int* __restrict__ cursor, int2* __restrict__ edge, int E)
{
    const int e = blockIdx.x * blockDim.x + threadIdx.x;
    if (e >= E) return;
    const int s = src[e];
    const int d = dst[e];
    const float sc = ssrc[s] + sdst[d];
    const float lr = sc >= 0.f ? sc : ALPHA * sc;
    const float w = __expf(-lr);
    const int pos = atomicAdd(&cursor[s], 1);
    edge[pos] = make_int2(d, __float_as_int(w));
}

// ---------------- aggregate: warp per node, unroll 8, fused elu ---------------
__global__ __launch_bounds__(512) void aggregate_kernel(
    const uint2* __restrict__ hh2, const int* __restrict__ off,
    const uint2* __restrict__ edge, float4* __restrict__ out4, int N)
{
    const int warp = (blockIdx.x * blockDim.x + threadIdx.x) >> 5;
    const int lane = threadIdx.x & 31;
    if (warp >= N) return;

    const int beg = off[warp];
    const int end = off[warp + 1];

    float ax = 0.f, ay = 0.f, az = 0.f, aw = 0.f, wsum = 0.f;

    int i = beg;
    for (; i + 8 <= end; i += 8) {
        uint2 ed[8]; uint2 u[8];
#pragma unroll
        for (int j = 0; j < 8; j++) ed[j] = edge[i + j];
#pragma unroll
        for (int j = 0; j < 8; j++) u[j] = hh2[(size_t)ed[j].x * 32 + lane];
#pragma unroll
        for (int j = 0; j < 8; j++) {
            const float w = __int_as_float((int)ed[j].y);
            float2 lo = __half22float2(*(const __half2*)&u[j].x);
            float2 hi = __half22float2(*(const __half2*)&u[j].y);
            ax = fmaf(w, lo.x, ax);
            ay = fmaf(w, lo.y, ay);
            az = fmaf(w, hi.x, az);
            aw = fmaf(w, hi.y, aw);
            wsum += w;
        }
    }
    for (; i < end; i++) {
        const uint2 ed = edge[i];
        const float w = __int_as_float((int)ed.y);
        const uint2 u = hh2[(size_t)ed.x * 32 + lane];
        float2 lo = __half22float2(*(const __half2*)&u.x);
        float2 hi = __half22float2(*(const __half2*)&u.y);
        ax = fmaf(w, lo.x, ax);
        ay = fmaf(w, lo.y, ay);
        az = fmaf(w, hi.x, az);
        aw = fmaf(w, hi.y, aw);
        wsum += w;
    }

    const float r = 1.f / (wsum + EPSV);
    ax *= r; ay *= r; az *= r; aw *= r;
    ax = ax > 0.f ? ax : expm1f(ax);
    ay = ay > 0.f ? ay : expm1f(ay);
    az = az > 0.f ? az : expm1f(az);
    aw = aw > 0.f ? aw : expm1f(aw);
    out4[(size_t)warp * 32 + lane] = make_float4(ax, ay, az, aw);
}

// ---------------- launch ------------------------------------------------------
extern "C" void kernel_launch(void* const* d_in, const int* in_sizes, int n_in,
                              void* d_out, int out_size)
{
    const float* x  = (const float*)d_in[0];
    const int*   ei = (const int*)d_in[1];      // JAX x64 disabled -> int32
    const float* W  = (const float*)d_in[2];
    const float* a  = (const float*)d_in[3];
    float* out = (float*)d_out;

    const int N = in_sizes[0] / IN_F;        // 50000
    const int E = in_sizes[1] / 2;           // 1600000
    const int* src = ei;
    const int* dst = ei + E;

    float *h, *ssrc, *sdst;
    __half* hh;
    int *deg, *off, *cursor, *part;
    int2* edge;
    cudaGetSymbolAddress((void**)&h,      g_h);
    cudaGetSymbolAddress((void**)&hh,     g_hh);
    cudaGetSymbolAddress((void**)&ssrc,   g_ssrc);
    cudaGetSymbolAddress((void**)&sdst,   g_sdst);
    cudaGetSymbolAddress((void**)&deg,    g_deg);
    cudaGetSymbolAddress((void**)&off,    g_off);
    cudaGetSymbolAddress((void**)&cursor, g_cursor);
    cudaGetSymbolAddress((void**)&part,   g_part);
    cudaGetSymbolAddress((void**)&edge,   g_edge);

    cudaMemsetAsync(deg, 0, (size_t)N_NODES * sizeof(int), 0);

    // CSR histogram
    hist_kernel<<<(E + 255) / 256, 256>>>(src, deg, E);

    // scan phases 1-2
    scan1_kernel<<<SCAN_NB, SCAN_BS>>>(deg, part, N);
    scan2_kernel<<<1, SCAN_BS>>>(part);

    // GEMM placed in the ncu-capture slot (5th launch) — no dependency on scan
    gemm_tf32_kernel<<<(N + GBM - 1) / GBM, 256>>>(x, W, h, N);

    // scan phase 3 (needs only deg + part)
    scan3_kernel<<<SCAN_NB, SCAN_BS>>>(deg, part, off, cursor, N, E);

    // per-node scores + fp16 mirror
    score_kernel<<<(N + 7) / 8, 256>>>(h, a, ssrc, sdst, hh, N);

    // scatter edges into CSR order + precompute weights (packed)
    scatter_kernel<<<(E + 255) / 256, 256>>>(src, dst, ssrc, sdst, cursor, edge, E);

    // aggregate per node (atomic-free, fp16 gather, unroll 8) + fused elu
    aggregate_kernel<<<(N * 32 + 511) / 512, 512>>>(
        (const uint2*)hh, off, (const uint2*)edge, (float4*)out, N);
}

// round 16
// speedup vs baseline: 1.3558x; 1.1514x over previous
#include <cuda_runtime.h>
#include <cuda_fp16.h>
#include <cuda_bf16.h>
#include <mma.h>
#include <math.h>

using namespace nvcuda;

#define N_NODES 50000
#define N_EDGES 1600000
#define IN_F    256
#define OUT_F   128
#define ALPHA   0.2f
#define EPSV    1e-9f

// GEMM tiling: 128x128 block tile, BK=16, double-buffered smem
#define GBM 128
#define GBN 128
#define GBK 16
#define N_PAD 50048   // 391 blocks * 128 rows

// scan config
#define SCAN_BS 256
#define SCAN_NB ((N_NODES + SCAN_BS - 1) / SCAN_BS)   // 196

// ---------------- scratch (device globals; no allocations allowed) ----------
__device__ float  g_h[(size_t)N_PAD * OUT_F];
__device__ __half g_hh[(size_t)N_NODES * OUT_F];
__device__ float  g_ssrc[N_NODES];
__device__ float  g_sdst[N_NODES];
__device__ int    g_deg[N_NODES];
__device__ int    g_off[N_NODES + 1];
__device__ int    g_cursor[N_NODES];
__device__ int    g_part[SCAN_NB];
__device__ int2   g_edge[N_EDGES];    // packed (dst, w bits)

// ---------------- GEMM: h = x @ W  (tf32, double-buffered) ------------------
// tf32 conversion happens at STAGING (registers -> smem), so the mma loop has
// zero cvt instructions. launch_bounds(256,2) caps regs at 128 -> 2 CTA/SM.
__global__ __launch_bounds__(256, 2) void gemm_tf32_kernel(
    const float* __restrict__ x, const float* __restrict__ W,
    float* __restrict__ h, int N)
{
    __shared__ float As[2][GBM][GBK + 4];
    __shared__ float Bs[2][GBK][GBN];

    const int tid = threadIdx.x;
    const int wid = tid >> 5;
    const int wm = wid >> 2;
    const int wn = wid & 3;
    const int row0 = blockIdx.x * GBM;

    const int ar0 = tid >> 2;
    const int ac  = (tid & 3) * 4;
    const int br0 = tid >> 5;
    const int bc  = (tid & 31) * 4;

    wmma::fragment<wmma::accumulator, 16, 16, 8, float> acc[4][2];
#pragma unroll
    for (int i = 0; i < 4; i++)
#pragma unroll
        for (int j = 0; j < 2; j++) wmma::fill_fragment(acc[i][j], 0.f);

    // preload chunk 0 (convert to tf32 at staging)
#pragma unroll
    for (int i = 0; i < 2; i++) {
        int grow = row0 + ar0 + i * 64; if (grow >= N) grow = N - 1;
        float4 av = *reinterpret_cast<const float4*>(x + (size_t)grow * IN_F + ac);
        float4 bv = *reinterpret_cast<const float4*>(W + (size_t)(br0 + i * 8) * GBN + bc);
        av.x = wmma::__float_to_tf32(av.x); av.y = wmma::__float_to_tf32(av.y);
        av.z = wmma::__float_to_tf32(av.z); av.w = wmma::__float_to_tf32(av.w);
        bv.x = wmma::__float_to_tf32(bv.x); bv.y = wmma::__float_to_tf32(bv.y);
        bv.z = wmma::__float_to_tf32(bv.z); bv.w = wmma::__float_to_tf32(bv.w);
        *reinterpret_cast<float4*>(&As[0][ar0 + i * 64][ac]) = av;
        *reinterpret_cast<float4*>(&Bs[0][br0 + i * 8][bc]) = bv;
    }
    __syncthreads();

    const int NIT = IN_F / GBK;   // 16
    for (int it = 0; it < NIT; it++) {
        const int cur = it & 1;
        float4 a_reg[2], b_reg[2];
        if (it + 1 < NIT) {
            const int k0 = (it + 1) * GBK;
#pragma unroll
            for (int i = 0; i < 2; i++) {
                int grow = row0 + ar0 + i * 64; if (grow >= N) grow = N - 1;
                a_reg[i] = *reinterpret_cast<const float4*>(x + (size_t)grow * IN_F + k0 + ac);
                b_reg[i] = *reinterpret_cast<const float4*>(W + (size_t)(k0 + br0 + i * 8) * GBN + bc);
            }
        }

#pragma unroll
        for (int ks = 0; ks < 2; ks++) {
            wmma::fragment<wmma::matrix_a, 16, 16, 8, wmma::precision::tf32, wmma::row_major> af[4];
#pragma unroll
            for (int mt = 0; mt < 4; mt++)
                wmma::load_matrix_sync(af[mt], &As[cur][wm * 64 + mt * 16][ks * 8], GBK + 4);
#pragma unroll
            for (int nt = 0; nt < 2; nt++) {
                wmma::fragment<wmma::matrix_b, 16, 16, 8, wmma::precision::tf32, wmma::row_major> bf;
                wmma::load_matrix_sync(bf, &Bs[cur][ks * 8][wn * 32 + nt * 16], GBN);
#pragma unroll
                for (int mt = 0; mt < 4; mt++)
                    wmma::mma_sync(acc[mt][nt], af[mt], bf, acc[mt][nt]);
            }
        }

        if (it + 1 < NIT) {
            const int nxt = 1 - cur;
#pragma unroll
            for (int i = 0; i < 2; i++) {
                a_reg[i].x = wmma::__float_to_tf32(a_reg[i].x);
                a_reg[i].y = wmma::__float_to_tf32(a_reg[i].y);
                a_reg[i].z = wmma::__float_to_tf32(a_reg[i].z);
                a_reg[i].w = wmma::__float_to_tf32(a_reg[i].w);
                b_reg[i].x = wmma::__float_to_tf32(b_reg[i].x);
                b_reg[i].y = wmma::__float_to_tf32(b_reg[i].y);
                b_reg[i].z = wmma::__float_to_tf32(b_reg[i].z);
                b_reg[i].w = wmma::__float_to_tf32(b_reg[i].w);
                *reinterpret_cast<float4*>(&As[nxt][ar0 + i * 64][ac]) = a_reg[i];
                *reinterpret_cast<float4*>(&Bs[nxt][br0 + i * 8][bc]) = b_reg[i];
            }
            __syncthreads();
        }
    }

#pragma unroll
    for (int mt = 0; mt < 4; mt++)
#pragma unroll
        for (int nt = 0; nt < 2; nt++)
            wmma::store_matrix_sync(
                h + (size_t)(row0 + wm * 64 + mt * 16) * OUT_F + wn * 32 + nt * 16,
                acc[mt][nt], OUT_F, wmma::mem_row_major);
}

// ---------------- per-node scores + fp16 mirror of h --------------------------
__global__ __launch_bounds__(256) void score_kernel(
    const float* __restrict__ h, const float* __restrict__ a,
    float* __restrict__ ssrc, float* __restrict__ sdst,
    __half* __restrict__ hh, int N)
{
    const int warp = (blockIdx.x * blockDim.x + threadIdx.x) >> 5;
    const int lane = threadIdx.x & 31;
    if (warp >= N) return;

    const float4 hv = reinterpret_cast<const float4*>(h + (size_t)warp * OUT_F)[lane];
    const float4 as = reinterpret_cast<const float4*>(a)[lane];
    const float4 ad = reinterpret_cast<const float4*>(a + OUT_F)[lane];

    __half2 p0 = __floats2half2_rn(hv.x, hv.y);
    __half2 p1 = __floats2half2_rn(hv.z, hv.w);
    reinterpret_cast<__half2*>(hh + (size_t)warp * OUT_F)[lane * 2]     = p0;
    reinterpret_cast<__half2*>(hh + (size_t)warp * OUT_F)[lane * 2 + 1] = p1;

    float s1 = hv.x * as.x + hv.y * as.y + hv.z * as.z + hv.w * as.w;
    float s2 = hv.x * ad.x + hv.y * ad.y + hv.z * ad.z + hv.w * ad.w;
#pragma unroll
    for (int o = 16; o > 0; o >>= 1) {
        s1 += __shfl_xor_sync(0xFFFFFFFFu, s1, o);
        s2 += __shfl_xor_sync(0xFFFFFFFFu, s2, o);
    }
    if (lane == 0) { ssrc[warp] = s1; sdst[warp] = s2; }
}

// ---------------- CSR build: histogram --------------------------------------
__global__ __launch_bounds__(256) void hist_kernel(
    const int* __restrict__ src, int* __restrict__ deg, int E)
{
    const int e = blockIdx.x * blockDim.x + threadIdx.x;
    if (e < E) atomicAdd(&deg[src[e]], 1);
}

// ---------------- scan phase 1: per-block sums --------------------------------
__global__ __launch_bounds__(SCAN_BS) void scan1_kernel(
    const int* __restrict__ deg, int* __restrict__ part, int N)
{
    __shared__ int sh[SCAN_BS];
    const int idx = blockIdx.x * SCAN_BS + threadIdx.x;
    int v = (idx < N) ? deg[idx] : 0;
    sh[threadIdx.x] = v;
    __syncthreads();
#pragma unroll
    for (int o = SCAN_BS / 2; o > 0; o >>= 1) {
        if (threadIdx.x < o) sh[threadIdx.x] += sh[threadIdx.x + o];
        __syncthreads();
    }
    if (threadIdx.x == 0) part[blockIdx.x] = sh[0];
}

// ---------------- scan phase 2: exclusive scan of partials (1 block) ----------
__global__ __launch_bounds__(SCAN_BS) void scan2_kernel(int* __restrict__ part)
{
    __shared__ int sh[SCAN_BS];
    const int t = threadIdx.x;
    int v = (t < SCAN_NB) ? part[t] : 0;
    sh[t] = v;
    __syncthreads();
#pragma unroll
    for (int o = 1; o < SCAN_BS; o <<= 1) {
        int u = (t >= o) ? sh[t - o] : 0;
        __syncthreads();
        sh[t] += u;
        __syncthreads();
    }
    if (t < SCAN_NB) part[t] = sh[t] - v;
}

// ---------------- scan phase 3: local scan + write offsets --------------------
__global__ __launch_bounds__(SCAN_BS) void scan3_kernel(
    const int* __restrict__ deg, const int* __restrict__ part,
    int* __restrict__ off, int* __restrict__ cursor, int N, int E)
{
    __shared__ int sh[SCAN_BS];
    const int t = threadIdx.x;
    const int idx = blockIdx.x * SCAN_BS + t;
    int v = (idx < N) ? deg[idx] : 0;
    sh[t] = v;
    __syncthreads();
#pragma unroll
    for (int o = 1; o < SCAN_BS; o <<= 1) {
        int u = (t >= o) ? sh[t - o] : 0;
        __syncthreads();
        sh[t] += u;
        __syncthreads();
    }
    if (idx < N) {
        const int o = part[blockIdx.x] + sh[t] - v;
        off[idx] = o;
        cursor[idx] = o;
        if (idx == N - 1) off[N] = E;
    }
}

// ---------------- CSR build: scatter + edge weights (packed int2) -------------
__global__ __launch_bounds__(256) void scatter_kernel(
    const int* __restrict__ src, const int* __restrict__ dst,
    const float* __restrict__ ssrc, const float* __restrict__ sdst,
    int* __restrict__ cursor, int2* __restrict__ edge, int E)
{
    const int e = blockIdx.x * blockDim.x + threadIdx.x;
    if (e >= E) return;
    const int s = src[e];
    const int d = dst[e];
    const float sc = ssrc[s] + sdst[d];
    const float lr = sc >= 0.f ? sc : ALPHA * sc;
    const float w = __expf(-lr);
    const int pos = atomicAdd(&cursor[s], 1);
    edge[pos] = make_int2(d, __float_as_int(w));
}

// ---------------- aggregate: warp per node, unroll 8, fused elu ---------------
__global__ __launch_bounds__(512) void aggregate_kernel(
    const uint2* __restrict__ hh2, const int* __restrict__ off,
    const uint2* __restrict__ edge, float4* __restrict__ out4, int N)
{
    const int warp = (blockIdx.x * blockDim.x + threadIdx.x) >> 5;
    const int lane = threadIdx.x & 31;
    if (warp >= N) return;

    const int beg = off[warp];
    const int end = off[warp + 1];

    float ax = 0.f, ay = 0.f, az = 0.f, aw = 0.f, wsum = 0.f;

    int i = beg;
    for (; i + 8 <= end; i += 8) {
        uint2 ed[8]; uint2 u[8];
#pragma unroll
        for (int j = 0; j < 8; j++) ed[j] = edge[i + j];
#pragma unroll
        for (int j = 0; j < 8; j++) u[j] = hh2[(size_t)ed[j].x * 32 + lane];
#pragma unroll
        for (int j = 0; j < 8; j++) {
            const float w = __int_as_float((int)ed[j].y);
            float2 lo = __half22float2(*(const __half2*)&u[j].x);
            float2 hi = __half22float2(*(const __half2*)&u[j].y);
            ax = fmaf(w, lo.x, ax);
            ay = fmaf(w, lo.y, ay);
            az = fmaf(w, hi.x, az);
            aw = fmaf(w, hi.y, aw);
            wsum += w;
        }
    }
    for (; i < end; i++) {
        const uint2 ed = edge[i];
        const float w = __int_as_float((int)ed.y);
        const uint2 u = hh2[(size_t)ed.x * 32 + lane];
        float2 lo = __half22float2(*(const __half2*)&u.x);
        float2 hi = __half22float2(*(const __half2*)&u.y);
        ax = fmaf(w, lo.x, ax);
        ay = fmaf(w, lo.y, ay);
        az = fmaf(w, hi.x, az);
        aw = fmaf(w, hi.y, aw);
        wsum += w;
    }

    const float r = 1.f / (wsum + EPSV);
    ax *= r; ay *= r; az *= r; aw *= r;
    ax = ax > 0.f ? ax : expm1f(ax);
    ay = ay > 0.f ? ay : expm1f(ay);
    az = az > 0.f ? az : expm1f(az);
    aw = aw > 0.f ? aw : expm1f(aw);
    out4[(size_t)warp * 32 + lane] = make_float4(ax, ay, az, aw);
}

// ---------------- launch ------------------------------------------------------
extern "C" void kernel_launch(void* const* d_in, const int* in_sizes, int n_in,
                              void* d_out, int out_size)
{
    const float* x  = (const float*)d_in[0];
    const int*   ei = (const int*)d_in[1];      // JAX x64 disabled -> int32
    const float* W  = (const float*)d_in[2];
    const float* a  = (const float*)d_in[3];
    float* out = (float*)d_out;

    const int N = in_sizes[0] / IN_F;        // 50000
    const int E = in_sizes[1] / 2;           // 1600000
    const int* src = ei;
    const int* dst = ei + E;

    float *h, *ssrc, *sdst;
    __half* hh;
    int *deg, *off, *cursor, *part;
    int2* edge;
    cudaGetSymbolAddress((void**)&h,      g_h);
    cudaGetSymbolAddress((void**)&hh,     g_hh);
    cudaGetSymbolAddress((void**)&ssrc,   g_ssrc);
    cudaGetSymbolAddress((void**)&sdst,   g_sdst);
    cudaGetSymbolAddress((void**)&deg,    g_deg);
    cudaGetSymbolAddress((void**)&off,    g_off);
    cudaGetSymbolAddress((void**)&cursor, g_cursor);
    cudaGetSymbolAddress((void**)&part,   g_part);
    cudaGetSymbolAddress((void**)&edge,   g_edge);

    cudaMemsetAsync(deg, 0, (size_t)N_NODES * sizeof(int), 0);

    // CSR histogram
    hist_kernel<<<(E + 255) / 256, 256>>>(src, deg, E);

    // scan phases 1-2
    scan1_kernel<<<SCAN_NB, SCAN_BS>>>(deg, part, N);
    scan2_kernel<<<1, SCAN_BS>>>(part);

    // GEMM kept in the ncu-capture slot (5th launch)
    gemm_tf32_kernel<<<(N + GBM - 1) / GBM, 256>>>(x, W, h, N);

    // scan phase 3 (needs only deg + part)
    scan3_kernel<<<SCAN_NB, SCAN_BS>>>(deg, part, off, cursor, N, E);

    // per-node scores + fp16 mirror
    score_kernel<<<(N + 7) / 8, 256>>>(h, a, ssrc, sdst, hh, N);

    // scatter edges into CSR order + precompute weights (packed)
    scatter_kernel<<<(E + 255) / 256, 256>>>(src, dst, ssrc, sdst, cursor, edge, E);

    // aggregate per node (atomic-free, fp16 gather, unroll 8) + fused elu
    aggregate_kernel<<<(N * 32 + 511) / 512, 512>>>(
        (const uint2*)hh, off, (const uint2*)edge, (float4*)out, N);
}

// round 17
// speedup vs baseline: 1.6158x; 1.1918x over previous
#include <cuda_runtime.h>
#include <cuda_fp16.h>
#include <cuda_bf16.h>
#include <mma.h>
#include <math.h>

using namespace nvcuda;

#define N_NODES 50000
#define N_EDGES 1600000
#define IN_F    256
#define OUT_F   128
#define ALPHA   0.2f
#define EPSV    1e-9f

// GEMM tiling: 128x128 block tile, BK=16, double-buffered fp16 smem
#define GBM 128
#define GBN 128
#define GBK 16
#define N_PAD 50048   // 391 blocks * 128 rows

#define AS_LD (GBK + 8)    // 24 halves = 48 B row stride (16B-aligned, bank-rotated)
#define BS_LD (GBN + 8)    // 136 halves = 272 B row stride

// scan config
#define SCAN_BS 256
#define SCAN_NB ((N_NODES + SCAN_BS - 1) / SCAN_BS)   // 196

// ---------------- scratch (device globals; no allocations allowed) ----------
__device__ float  g_h[(size_t)N_PAD * OUT_F];
__device__ __half g_hh[(size_t)N_NODES * OUT_F];
__device__ float  g_ssrc[N_NODES];
__device__ float  g_sdst[N_NODES];
__device__ int    g_deg[N_NODES];
__device__ int    g_off[N_NODES + 1];
__device__ int    g_cursor[N_NODES];
__device__ int    g_part[SCAN_NB];
__device__ int2   g_edge[N_EDGES];    // packed (dst, w bits)

// float4 -> 4 halves packed in uint2
__device__ __forceinline__ uint2 f4_to_h4(float4 v) {
    __half2 lo = __floats2half2_rn(v.x, v.y);
    __half2 hi = __floats2half2_rn(v.z, v.w);
    uint2 r;
    r.x = *reinterpret_cast<unsigned*>(&lo);
    r.y = *reinterpret_cast<unsigned*>(&hi);
    return r;
}

// ---------------- GEMM: h = x @ W  (fp16 mma m16n16k16, fp32 accum) ---------
// fp16 conversion at STAGING; mma loop is cvt-free. One 16-deep k-step per
// chunk -> half the mma instructions and half the smem fragment traffic vs tf32.
__global__ __launch_bounds__(256, 2) void gemm_fp16_kernel(
    const float* __restrict__ x, const float* __restrict__ W,
    float* __restrict__ h, int N)
{
    __shared__ __half As[2][GBM][AS_LD];   // 2*128*24*2 = 12 KB
    __shared__ __half Bs[2][GBK][BS_LD];   // 2*16*136*2 = 8.5 KB

    const int tid = threadIdx.x;
    const int wid = tid >> 5;
    const int wm = wid >> 2;       // 0..1 -> 64 rows
    const int wn = wid & 3;        // 0..3 -> 32 cols
    const int row0 = blockIdx.x * GBM;

    const int ar0 = tid >> 2;            // A rows: +0, +64
    const int ac  = (tid & 3) * 4;       // A col (float4)
    const int br0 = tid >> 5;            // B rows: +0, +8
    const int bc  = (tid & 31) * 4;      // B col (float4)

    wmma::fragment<wmma::accumulator, 16, 16, 16, float> acc[4][2];
#pragma unroll
    for (int i = 0; i < 4; i++)
#pragma unroll
        for (int j = 0; j < 2; j++) wmma::fill_fragment(acc[i][j], 0.f);

    // preload chunk 0 (convert to fp16 at staging)
#pragma unroll
    for (int i = 0; i < 2; i++) {
        int grow = row0 + ar0 + i * 64; if (grow >= N) grow = N - 1;
        float4 av = *reinterpret_cast<const float4*>(x + (size_t)grow * IN_F + ac);
        float4 bv = *reinterpret_cast<const float4*>(W + (size_t)(br0 + i * 8) * GBN + bc);
        *reinterpret_cast<uint2*>(&As[0][ar0 + i * 64][ac]) = f4_to_h4(av);
        *reinterpret_cast<uint2*>(&Bs[0][br0 + i * 8][bc]) = f4_to_h4(bv);
    }
    __syncthreads();

    const int NIT = IN_F / GBK;   // 16
    for (int it = 0; it < NIT; it++) {
        const int cur = it & 1;
        float4 a_reg[2], b_reg[2];
        if (it + 1 < NIT) {
            const int k0 = (it + 1) * GBK;
#pragma unroll
            for (int i = 0; i < 2; i++) {
                int grow = row0 + ar0 + i * 64; if (grow >= N) grow = N - 1;
                a_reg[i] = *reinterpret_cast<const float4*>(x + (size_t)grow * IN_F + k0 + ac);
                b_reg[i] = *reinterpret_cast<const float4*>(W + (size_t)(k0 + br0 + i * 8) * GBN + bc);
            }
        }

        // single 16-deep k-step
        {
            wmma::fragment<wmma::matrix_a, 16, 16, 16, __half, wmma::row_major> af[4];
#pragma unroll
            for (int mt = 0; mt < 4; mt++)
                wmma::load_matrix_sync(af[mt], &As[cur][wm * 64 + mt * 16][0], AS_LD);
#pragma unroll
            for (int nt = 0; nt < 2; nt++) {
                wmma::fragment<wmma::matrix_b, 16, 16, 16, __half, wmma::row_major> bf;
                wmma::load_matrix_sync(bf, &Bs[cur][0][wn * 32 + nt * 16], BS_LD);
#pragma unroll
                for (int mt = 0; mt < 4; mt++)
                    wmma::mma_sync(acc[mt][nt], af[mt], bf, acc[mt][nt]);
            }
        }

        if (it + 1 < NIT) {
            const int nxt = 1 - cur;
#pragma unroll
            for (int i = 0; i < 2; i++) {
                *reinterpret_cast<uint2*>(&As[nxt][ar0 + i * 64][ac]) = f4_to_h4(a_reg[i]);
                *reinterpret_cast<uint2*>(&Bs[nxt][br0 + i * 8][bc]) = f4_to_h4(b_reg[i]);
            }
            __syncthreads();
        }
    }

#pragma unroll
    for (int mt = 0; mt < 4; mt++)
#pragma unroll
        for (int nt = 0; nt < 2; nt++)
            wmma::store_matrix_sync(
                h + (size_t)(row0 + wm * 64 + mt * 16) * OUT_F + wn * 32 + nt * 16,
                acc[mt][nt], OUT_F, wmma::mem_row_major);
}

// ---------------- per-node scores + fp16 mirror of h --------------------------
__global__ __launch_bounds__(256) void score_kernel(
    const float* __restrict__ h, const float* __restrict__ a,
    float* __restrict__ ssrc, float* __restrict__ sdst,
    __half* __restrict__ hh, int N)
{
    const int warp = (blockIdx.x * blockDim.x + threadIdx.x) >> 5;
    const int lane = threadIdx.x & 31;
    if (warp >= N) return;

    const float4 hv = reinterpret_cast<const float4*>(h + (size_t)warp * OUT_F)[lane];
    const float4 as = reinterpret_cast<const float4*>(a)[lane];
    const float4 ad = reinterpret_cast<const float4*>(a + OUT_F)[lane];

    __half2 p0 = __floats2half2_rn(hv.x, hv.y);
    __half2 p1 = __floats2half2_rn(hv.z, hv.w);
    reinterpret_cast<__half2*>(hh + (size_t)warp * OUT_F)[lane * 2]     = p0;
    reinterpret_cast<__half2*>(hh + (size_t)warp * OUT_F)[lane * 2 + 1] = p1;

    float s1 = hv.x * as.x + hv.y * as.y + hv.z * as.z + hv.w * as.w;
    float s2 = hv.x * ad.x + hv.y * ad.y + hv.z * ad.z + hv.w * ad.w;
#pragma unroll
    for (int o = 16; o > 0; o >>= 1) {
        s1 += __shfl_xor_sync(0xFFFFFFFFu, s1, o);
        s2 += __shfl_xor_sync(0xFFFFFFFFu, s2, o);
    }
    if (lane == 0) { ssrc[warp] = s1; sdst[warp] = s2; }
}

// ---------------- CSR build: histogram --------------------------------------
__global__ __launch_bounds__(256) void hist_kernel(
    const int* __restrict__ src, int* __restrict__ deg, int E)
{
    const int e = blockIdx.x * blockDim.x + threadIdx.x;
    if (e < E) atomicAdd(&deg[src[e]], 1);
}

// ---------------- scan phase 1: per-block sums --------------------------------
__global__ __launch_bounds__(SCAN_BS) void scan1_kernel(
    const int* __restrict__ deg, int* __restrict__ part, int N)
{
    __shared__ int sh[SCAN_BS];
    const int idx = blockIdx.x * SCAN_BS + threadIdx.x;
    int v = (idx < N) ? deg[idx] : 0;
    sh[threadIdx.x] = v;
    __syncthreads();
#pragma unroll
    for (int o = SCAN_BS / 2; o > 0; o >>= 1) {
        if (threadIdx.x < o) sh[threadIdx.x] += sh[threadIdx.x + o];
        __syncthreads();
    }
    if (threadIdx.x == 0) part[blockIdx.x] = sh[0];
}

// ---------------- scan phase 2: exclusive scan of partials (1 block) ----------
__global__ __launch_bounds__(SCAN_BS) void scan2_kernel(int* __restrict__ part)
{
    __shared__ int sh[SCAN_BS];
    const int t = threadIdx.x;
    int v = (t < SCAN_NB) ? part[t] : 0;
    sh[t] = v;
    __syncthreads();
#pragma unroll
    for (int o = 1; o < SCAN_BS; o <<= 1) {
        int u = (t >= o) ? sh[t - o] : 0;
        __syncthreads();
        sh[t] += u;
        __syncthreads();
    }
    if (t < SCAN_NB) part[t] = sh[t] - v;
}

// ---------------- scan phase 3: local scan + write offsets --------------------
__global__ __launch_bounds__(SCAN_BS) void scan3_kernel(
    const int* __restrict__ deg, const int* __restrict__ part,
    int* __restrict__ off, int* __restrict__ cursor, int N, int E)
{
    __shared__ int sh[SCAN_BS];
    const int t = threadIdx.x;
    const int idx = blockIdx.x * SCAN_BS + t;
    int v = (idx < N) ? deg[idx] : 0;
    sh[t] = v;
    __syncthreads();
#pragma unroll
    for (int o = 1; o < SCAN_BS; o <<= 1) {
        int u = (t >= o) ? sh[t - o] : 0;
        __syncthreads();
        sh[t] += u;
        __syncthreads();
    }
    if (idx < N) {
        const int o = part[blockIdx.x] + sh[t] - v;
        off[idx] = o;
        cursor[idx] = o;
        if (idx == N - 1) off[N] = E;
    }
}

// ---------------- CSR build: scatter + edge weights (packed int2) -------------
__global__ __launch_bounds__(256) void scatter_kernel(
    const int* __restrict__ src, const int* __restrict__ dst,
    const float* __restrict__ ssrc, const float* __restrict__ sdst,
    int* __restrict__ cursor, int2* __restrict__ edge, int E)
{
    const int e = blockIdx.x * blockDim.x + threadIdx.x;
    if (e >= E) return;
    const int s = src[e];
    const int d = dst[e];
    const float sc = ssrc[s] + sdst[d];
    const float lr = sc >= 0.f ? sc : ALPHA * sc;
    const float w = __expf(-lr);
    const int pos = atomicAdd(&cursor[s], 1);
    edge[pos] = make_int2(d, __float_as_int(w));
}

// ---------------- aggregate: warp per node, unroll 8, fused elu ---------------
__global__ __launch_bounds__(512) void aggregate_kernel(
    const uint2* __restrict__ hh2, const int* __restrict__ off,
    const uint2* __restrict__ edge, float4* __restrict__ out4, int N)
{
    const int warp = (blockIdx.x * blockDim.x + threadIdx.x) >> 5;
    const int lane = threadIdx.x & 31;
    if (warp >= N) return;

    const int beg = off[warp];
    const int end = off[warp + 1];

    float ax = 0.f, ay = 0.f, az = 0.f, aw = 0.f, wsum = 0.f;

    int i = beg;
    for (; i + 8 <= end; i += 8) {
        uint2 ed[8]; uint2 u[8];
#pragma unroll
        for (int j = 0; j < 8; j++) ed[j] = edge[i + j];
#pragma unroll
        for (int j = 0; j < 8; j++) u[j] = hh2[(size_t)ed[j].x * 32 + lane];
#pragma unroll
        for (int j = 0; j < 8; j++) {
            const float w = __int_as_float((int)ed[j].y);
            float2 lo = __half22float2(*(const __half2*)&u[j].x);
            float2 hi = __half22float2(*(const __half2*)&u[j].y);
            ax = fmaf(w, lo.x, ax);
            ay = fmaf(w, lo.y, ay);
            az = fmaf(w, hi.x, az);
            aw = fmaf(w, hi.y, aw);
            wsum += w;
        }
    }
    for (; i < end; i++) {
        const uint2 ed = edge[i];
        const float w = __int_as_float((int)ed.y);
        const uint2 u = hh2[(size_t)ed.x * 32 + lane];
        float2 lo = __half22float2(*(const __half2*)&u.x);
        float2 hi = __half22float2(*(const __half2*)&u.y);
        ax = fmaf(w, lo.x, ax);
        ay = fmaf(w, lo.y, ay);
        az = fmaf(w, hi.x, az);
        aw = fmaf(w, hi.y, aw);
        wsum += w;
    }

    const float r = 1.f / (wsum + EPSV);
    ax *= r; ay *= r; az *= r; aw *= r;
    ax = ax > 0.f ? ax : expm1f(ax);
    ay = ay > 0.f ? ay : expm1f(ay);
    az = az > 0.f ? az : expm1f(az);
    aw = aw > 0.f ? aw : expm1f(aw);
    out4[(size_t)warp * 32 + lane] = make_float4(ax, ay, az, aw);
}

// ---------------- launch ------------------------------------------------------
extern "C" void kernel_launch(void* const* d_in, const int* in_sizes, int n_in,
                              void* d_out, int out_size)
{
    const float* x  = (const float*)d_in[0];
    const int*   ei = (const int*)d_in[1];      // JAX x64 disabled -> int32
    const float* W  = (const float*)d_in[2];
    const float* a  = (const float*)d_in[3];
    float* out = (float*)d_out;

    const int N = in_sizes[0] / IN_F;        // 50000
    const int E = in_sizes[1] / 2;           // 1600000
    const int* src = ei;
    const int* dst = ei + E;

    float *h, *ssrc, *sdst;
    __half* hh;
    int *deg, *off, *cursor, *part;
    int2* edge;
    cudaGetSymbolAddress((void**)&h,      g_h);
    cudaGetSymbolAddress((void**)&hh,     g_hh);
    cudaGetSymbolAddress((void**)&ssrc,   g_ssrc);
    cudaGetSymbolAddress((void**)&sdst,   g_sdst);
    cudaGetSymbolAddress((void**)&deg,    g_deg);
    cudaGetSymbolAddress((void**)&off,    g_off);
    cudaGetSymbolAddress((void**)&cursor, g_cursor);
    cudaGetSymbolAddress((void**)&part,   g_part);
    cudaGetSymbolAddress((void**)&edge,   g_edge);

    cudaMemsetAsync(deg, 0, (size_t)N_NODES * sizeof(int), 0);

    // CSR histogram
    hist_kernel<<<(E + 255) / 256, 256>>>(src, deg, E);

    // scan phases 1-2
    scan1_kernel<<<SCAN_NB, SCAN_BS>>>(deg, part, N);
    scan2_kernel<<<1, SCAN_BS>>>(part);

    // GEMM kept in the ncu-capture slot (5th launch)
    gemm_fp16_kernel<<<(N + GBM - 1) / GBM, 256>>>(x, W, h, N);

    // scan phase 3 (needs only deg + part)
    scan3_kernel<<<SCAN_NB, SCAN_BS>>>(deg, part, off, cursor, N, E);

    // per-node scores + fp16 mirror
    score_kernel<<<(N + 7) / 8, 256>>>(h, a, ssrc, sdst, hh, N);

    // scatter edges into CSR order + precompute weights (packed)
    scatter_kernel<<<(E + 255) / 256, 256>>>(src, dst, ssrc, sdst, cursor, edge, E);

    // aggregate per node (atomic-free, fp16 gather, unroll 8) + fused elu
    aggregate_kernel<<<(N * 32 + 511) / 512, 512>>>(
        (const uint2*)hh, off, (const uint2*)edge, (float4*)out, N);
}